// round 14
// baseline (speedup 1.0000x reference)
#include <cuda_runtime.h>
#include <cuda_fp16.h>
#include <math.h>
#include <float.h>
#include <stdint.h>

// ---------------- problem constants ----------------
constexpr int NB  = 4;
constexpr int NS  = 1024;
constexpr int ND  = 1024;
constexpr int NH  = 16;
constexpr int NHD = 64;
constexpr int NE  = 8;
constexpr int NF  = 4096;
constexpr int NT  = NB * NS;            // 4096 tokens
constexpr float EPS = 1e-5f;

// ---------------- scratch (device globals; no runtime alloc) ----------------
__device__ __half g_x16[(size_t)NT * ND];
__device__ __half g_inwh[(size_t)3 * ND * ND];
__device__ __half g_outwh[(size_t)ND * ND];
__device__ __half g_w1t[(size_t)NE * NF * ND];      // [E][F][D] fp16 (transposed)
__device__ __half g_w2t[(size_t)NE * ND * NF];      // [E][D][F] fp16 (transposed)
__device__ __half g_qkvh[(size_t)NT * 3 * ND];
__device__ __half g_attnoh[(size_t)NT * ND];
__device__ __half g_x1h[(size_t)NT * ND];
__device__ __half g_h[(size_t)(NT + 128) * NF];     // fp16 hidden
__device__ float  g_tmp[(size_t)NT * ND];
__device__ float  g_x1[(size_t)NT * ND];
__device__ int    g_idx[NT];
__device__ int    g_order[NT];
__device__ int    g_cnt[NE];
__device__ int    g_off[NE + 1];
__device__ int    g_pos[NE];

// ---------------- helpers ----------------
__device__ __forceinline__ uint32_t f2h2(float lo, float hi) {
    __half2 h = __floats2half2_rn(lo, hi);
    return *reinterpret_cast<uint32_t*>(&h);
}
__device__ __forceinline__ uint32_t smem_u32(const void* p) {
    uint32_t a;
    asm("{ .reg .u64 t; cvta.to.shared.u64 t, %1; cvt.u32.u64 %0, t; }" : "=r"(a) : "l"(p));
    return a;
}
__device__ __forceinline__ void mma_f16(float c[4], const uint32_t a[4],
                                        uint32_t b0, uint32_t b1) {
    asm volatile(
        "mma.sync.aligned.m16n8k16.row.col.f32.f16.f16.f32 "
        "{%0,%1,%2,%3}, {%4,%5,%6,%7}, {%8,%9}, {%0,%1,%2,%3};"
        : "+f"(c[0]), "+f"(c[1]), "+f"(c[2]), "+f"(c[3])
        : "r"(a[0]), "r"(a[1]), "r"(a[2]), "r"(a[3]), "r"(b0), "r"(b1));
}
__device__ __forceinline__ void ldsm_x4(uint32_t d[4], uint32_t addr) {
    asm volatile("ldmatrix.sync.aligned.m8n8.x4.shared.b16 {%0,%1,%2,%3}, [%4];"
                 : "=r"(d[0]), "=r"(d[1]), "=r"(d[2]), "=r"(d[3]) : "r"(addr));
}
__device__ __forceinline__ void cpa16(uint32_t saddr, const void* gptr, bool valid) {
    const int sz = valid ? 16 : 0;
    asm volatile("cp.async.cg.shared.global [%0], [%1], 16, %2;"
                 :: "r"(saddr), "l"(gptr), "r"(sz));
}
#define CP_COMMIT()  asm volatile("cp.async.commit_group;")
#define CP_WAIT2()   asm volatile("cp.async.wait_group 2;")

// fast 2^y for y <= 0, FMA pipe only. |rel err| ~3e-6.
__device__ __forceinline__ float exp2p(float y) {
    y = fmaxf(y, -80.f);
    const int ni = __float2int_rn(y);
    const float f = y - (float)ni;
    float p = 0.0013333558146428443f;
    p = fmaf(p, f, 0.009618129107628477f);
    p = fmaf(p, f, 0.05550410866482158f);
    p = fmaf(p, f, 0.2402265069591007f);
    p = fmaf(p, f, 0.6931471805599453f);
    p = fmaf(p, f, 1.0f);
    return __uint_as_float(__float_as_uint(p) + ((uint32_t)ni << 23));
}

// ---------------- conversion kernels ----------------
__global__ __launch_bounds__(256) void cvt_f32_f16(
    const float* __restrict__ src, __half* __restrict__ dst, int n4)
{
    const int i = blockIdx.x * 256 + threadIdx.x;
    if (i < n4) {
        float4 v = reinterpret_cast<const float4*>(src)[i];
        uint2 u;
        u.x = f2h2(v.x, v.y);
        u.y = f2h2(v.z, v.w);
        reinterpret_cast<uint2*>(dst)[i] = u;
    }
}

// transpose + convert: src [Kd][Nd] fp32 -> dst [Nd][Kd] fp16, per expert (blockIdx.z)
__global__ __launch_bounds__(256) void transpose_cvt(
    const float* __restrict__ src, __half* __restrict__ dst, int Kd, int Nd)
{
    __shared__ float t[64][33];
    const size_t eofs = (size_t)blockIdx.z * (size_t)Kd * Nd;
    const int n0 = blockIdx.x * 32;
    const int k0 = blockIdx.y * 64;
    const int tx = threadIdx.x & 31;
    const int ty = threadIdx.x >> 5;   // 0..7
#pragma unroll
    for (int i = 0; i < 8; ++i)
        t[ty + i * 8][tx] = src[eofs + (size_t)(k0 + ty + i * 8) * Nd + n0 + tx];
    __syncthreads();
    const int nl = threadIdx.x >> 3;   // 0..31
    const int kc = threadIdx.x & 7;    // 0..7
    __half* drow = dst + eofs + (size_t)(n0 + nl) * Kd + k0;
#pragma unroll
    for (int j = 0; j < 4; ++j) {
        const int k2 = kc + j * 8;     // half2 index 0..31
        __half2 h = __floats2half2_rn(t[2 * k2][nl], t[2 * k2 + 1][nl]);
        *reinterpret_cast<__half2*>(drow + 2 * k2) = h;
    }
}

// ================= fp16 GEMM: 4 warps x (64x64), cp.async 4-stage, ldmatrix ========
// (BK=32, 4 stages, 3 in flight; fragment loads software-pipelined)
constexpr int G_ASTG = 2560;                 // [128][20] words per stage
constexpr int G_BOFF = 4 * G_ASTG;           // 10240
constexpr int GEMM_SMEM_BYTES = 8 * G_ASTG * 4;   // 81920 B

template<int MODE>
__global__ void __launch_bounds__(128, 2) gemm_f16(
    const __half* __restrict__ A, int lda,
    const __half* __restrict__ B, int ldb,
    const float* __restrict__ bias,
    void* __restrict__ Cv, int ldc,
    int K, int Nglob)
{
    extern __shared__ uint32_t smw[];
    __shared__ int tok[128];

    const int tid = threadIdx.x;
    const int wid = tid >> 5;           // 0..3
    const int ln  = tid & 31;
    const int wm  = wid >> 1;           // 0..1 -> 64-row slice
    const int wn  = wid & 1;            // 0..1 -> 64-col slice
    const int m0 = blockIdx.x * 128;
    const int n0 = blockIdx.y * 128;

    int seg0 = 0, seg1 = 1 << 30;
    const __half* Bp = B;
    const float* biasp = bias;
    if (MODE >= 2) {
        const int e = blockIdx.z;
        seg0 = g_off[e]; seg1 = g_off[e + 1];
        if (seg0 + m0 >= seg1) return;
        Bp    = B + (size_t)e * K * Nglob;
        biasp = bias + (size_t)e * Nglob;
        {
            const int p = seg0 + m0 + tid;
            tok[tid] = (p < seg1) ? g_order[p] : -1;
        }
        __syncthreads();
    }

    const uint32_t sbase = smem_u32(smw);

    const uint32_t aoff0 = ((uint32_t)(wm * 64 + (ln & 15)) * 20u + (uint32_t)(ln >> 4) * 4u) * 4u;
    const uint32_t brow = (uint32_t)(wn * 64) + (uint32_t)(((ln >> 4) << 3) | (ln & 7));
    const uint32_t boff0 = (brow * 20u + (uint32_t)((ln >> 3) & 1) * 4u) * 4u;

    float acc[4][8][4];
#pragma unroll
    for (int mt = 0; mt < 4; ++mt)
#pragma unroll
        for (int nt = 0; nt < 8; ++nt)
#pragma unroll
            for (int r = 0; r < 4; ++r) acc[mt][nt][r] = 0.f;

    const int nK = K >> 5;

    auto issue = [&](int kt) {
        const int k0 = kt << 5;
        const int s = kt & 3;
        const uint32_t sA = sbase + (s * G_ASTG) * 4;
        const uint32_t sB = sbase + (G_BOFF + s * G_ASTG) * 4;
#pragma unroll
        for (int it = 0; it < 4; ++it) {
            const int idx = tid + it * 128;   // 0..511
            const int row = idx >> 2;         // 0..127
            const int c   = idx & 3;          // 16B chunk
            const __half* ga;
            bool vA = true;
            if (MODE == 2) {
                const int tk = tok[row];
                vA = (tk >= 0);
                ga = A + (size_t)(vA ? tk : 0) * lda + k0 + c * 8;
            } else if (MODE == 3) {
                ga = A + (size_t)(seg0 + m0 + row) * lda + k0 + c * 8;
            } else {
                ga = A + (size_t)(m0 + row) * lda + k0 + c * 8;
            }
            cpa16(sA + (row * 20 + c * 4) * 4, ga, vA);
            const __half* gb = Bp + (size_t)(n0 + row) * ldb + k0 + c * 8;
            cpa16(sB + (row * 20 + c * 4) * 4, gb, true);
        }
    };
    auto compute = [&](int kt) {
        const int s = kt & 3;
        const uint32_t aab = sbase + (s * G_ASTG) * 4 + aoff0;
        const uint32_t bab = sbase + ((G_BOFF + s * G_ASTG)) * 4 + boff0;

        uint32_t afb[2][4][4];      // double-buffered A fragments (per ks)
        uint32_t bfb[2][4];         // double-buffered B fragments (per q)
#pragma unroll
        for (int mt = 0; mt < 4; ++mt) ldsm_x4(afb[0][mt], aab + (uint32_t)mt * 1280u);
        ldsm_x4(bfb[0], bab);

#pragma unroll
        for (int ks = 0; ks < 2; ++ks) {
            const uint32_t kofs = (uint32_t)ks * 32u;
            if (ks == 0) {
#pragma unroll
                for (int mt = 0; mt < 4; ++mt)
                    ldsm_x4(afb[1][mt], aab + (uint32_t)mt * 1280u + 32u);
            }
#pragma unroll
            for (int q = 0; q < 4; ++q) {
                if (q < 3) {
                    ldsm_x4(bfb[(q + 1) & 1], bab + (uint32_t)(q + 1) * 1280u + kofs);
                } else if (ks == 0) {
                    ldsm_x4(bfb[0], bab + 32u);      // next: ks=1, q=0 (parity 0)
                }
                const uint32_t* bf = bfb[q & 1];
#pragma unroll
                for (int mt = 0; mt < 4; ++mt) {
                    mma_f16(acc[mt][2 * q],     afb[ks][mt], bf[0], bf[1]);
                    mma_f16(acc[mt][2 * q + 1], afb[ks][mt], bf[2], bf[3]);
                }
            }
        }
    };

    issue(0); CP_COMMIT();
    issue(1); CP_COMMIT();
    issue(2); CP_COMMIT();
    for (int kt = 0; kt < nK; ++kt) {
        CP_WAIT2();
        __syncthreads();
        if (kt + 3 < nK) issue(kt + 3);
        CP_COMMIT();
        compute(kt);
    }

    const int lr = ln >> 2;
    const int lc = ln & 3;
#pragma unroll
    for (int mt = 0; mt < 4; ++mt) {
#pragma unroll
        for (int half = 0; half < 2; ++half) {
            const int lrow = wm * 64 + mt * 16 + half * 8 + lr;
            bool valid = true;
            size_t rowidx = 0;
            if (MODE == 0 || MODE == 1) {
                rowidx = (size_t)(m0 + lrow);
            } else if (MODE == 2) {
                const int p = seg0 + m0 + lrow;
                valid = (p < seg1);
                rowidx = (size_t)p;
            } else {
                const int tk = tok[lrow];
                valid = (tk >= 0);
                rowidx = (size_t)(valid ? tk : 0);
            }
            if (!valid) continue;
#pragma unroll
            for (int nt = 0; nt < 8; ++nt) {
                const int cc = n0 + wn * 64 + nt * 8 + lc * 2;
                float vx = acc[mt][nt][half * 2 + 0] + biasp[cc];
                float vy = acc[mt][nt][half * 2 + 1] + biasp[cc + 1];
                if (MODE == 0) {
                    uint32_t* dst = (uint32_t*)Cv + rowidx * (ldc >> 1) + (cc >> 1);
                    *dst = f2h2(vx, vy);
                } else if (MODE == 2) {
                    vx = fmaxf(vx, 0.f); vy = fmaxf(vy, 0.f);
                    uint32_t* dst = (uint32_t*)Cv + rowidx * (ldc >> 1) + (cc >> 1);
                    *dst = f2h2(vx, vy);
                } else {
                    float2 v; v.x = vx; v.y = vy;
                    *reinterpret_cast<float2*>((float*)Cv + rowidx * ldc + cc) = v;
                }
            }
        }
    }
}

// ================= fp16 flash attention with register-prefetched K/V =================
__global__ void __launch_bounds__(256, 2) flash_attn_f16(
    const __half* __restrict__ qkvh, __half* __restrict__ Oh)
{
    __shared__ uint32_t sQ[128 * 36];
    __shared__ uint32_t sK[64 * 36];
    __shared__ uint32_t sVt[32 * 72];

    const int tid = threadIdx.x;
    const int wid = tid >> 5;
    const int ln  = tid & 31;
    const int lr  = ln >> 2;
    const int lc  = ln & 3;
    const int b   = blockIdx.y >> 4;
    const int h   = blockIdx.y & 15;
    const int q0  = blockIdx.x * 128;
    const int wq  = wid * 16;
    const float qscale = 0.18033688011112042f;   // log2(e) / sqrt(64)

    const uint32_t* qkw = reinterpret_cast<const uint32_t*>(qkvh);   // 1536 words/row

#pragma unroll
    for (int it = 0; it < 4; ++it) {
        const int idx = tid + it * 256;
        const int row = idx >> 3;
        const int c   = idx & 7;
        const uint32_t* src = qkw + (size_t)(b * NS + q0 + row) * 1536 + h * 32 + c * 4;
        *reinterpret_cast<uint4*>(&sQ[row * 36 + c * 4]) = *reinterpret_cast<const uint4*>(src);
    }

    uint4 pk[2];
    uint4 pvlo, pvhi;
    const int krow0 = tid >> 3;
    const int kc0   = tid & 7;
    const int vk2   = tid >> 3;
    const int vdc   = tid & 7;

    auto loadRegs = [&](int kb) {
#pragma unroll
        for (int it = 0; it < 2; ++it) {
            const int row = krow0 + it * 32;
            const uint32_t* src = qkw + (size_t)(b * NS + kb * 64 + row) * 1536 + 512 + h * 32 + kc0 * 4;
            pk[it] = *reinterpret_cast<const uint4*>(src);
        }
        const uint32_t* vb = qkw + (size_t)(b * NS + kb * 64 + 2 * vk2) * 1536 + 1024 + h * 32 + vdc * 4;
        pvlo = *reinterpret_cast<const uint4*>(vb);
        pvhi = *reinterpret_cast<const uint4*>(vb + 1536);
    };
    auto storeRegs = [&]() {
#pragma unroll
        for (int it = 0; it < 2; ++it) {
            const int row = krow0 + it * 32;
            *reinterpret_cast<uint4*>(&sK[row * 36 + kc0 * 4]) = pk[it];
        }
        uint4 w0, w1;
        w0.x = __byte_perm(pvlo.x, pvhi.x, 0x5410); w0.y = __byte_perm(pvlo.x, pvhi.x, 0x7632);
        w0.z = __byte_perm(pvlo.y, pvhi.y, 0x5410); w0.w = __byte_perm(pvlo.y, pvhi.y, 0x7632);
        w1.x = __byte_perm(pvlo.z, pvhi.z, 0x5410); w1.y = __byte_perm(pvlo.z, pvhi.z, 0x7632);
        w1.z = __byte_perm(pvlo.w, pvhi.w, 0x5410); w1.w = __byte_perm(pvlo.w, pvhi.w, 0x7632);
        *reinterpret_cast<uint4*>(&sVt[vk2 * 72 + vdc * 8]) = w0;
        *reinterpret_cast<uint4*>(&sVt[vk2 * 72 + vdc * 8 + 4]) = w1;
    };

    float mr0 = -1e30f, mr1 = -1e30f;
    float l0 = 0.f, l1 = 0.f;
    float o[8][4];
#pragma unroll
    for (int jd = 0; jd < 8; ++jd)
#pragma unroll
        for (int r = 0; r < 4; ++r) o[jd][r] = 0.f;

    loadRegs(0);
    storeRegs();
    __syncthreads();

    for (int kb = 0; kb < 16; ++kb) {
        if (kb + 1 < 16) loadRegs(kb + 1);

        float s[8][4];
#pragma unroll
        for (int jn = 0; jn < 8; ++jn)
#pragma unroll
            for (int r = 0; r < 4; ++r) s[jn][r] = 0.f;
#pragma unroll
        for (int kk = 0; kk < 4; ++kk) {
            uint32_t a[4];
            a[0] = sQ[(wq + lr) * 36 + kk * 8 + lc];
            a[1] = sQ[(wq + lr + 8) * 36 + kk * 8 + lc];
            a[2] = sQ[(wq + lr) * 36 + kk * 8 + 4 + lc];
            a[3] = sQ[(wq + lr + 8) * 36 + kk * 8 + 4 + lc];
#pragma unroll
            for (int jn = 0; jn < 8; ++jn) {
                const uint32_t b0 = sK[(jn * 8 + lr) * 36 + kk * 8 + lc];
                const uint32_t b1 = sK[(jn * 8 + lr) * 36 + kk * 8 + 4 + lc];
                mma_f16(s[jn], a, b0, b1);
            }
        }
#pragma unroll
        for (int jn = 0; jn < 8; ++jn)
#pragma unroll
            for (int r = 0; r < 4; ++r) s[jn][r] *= qscale;

        float mx0 = s[0][0], mx1 = s[0][2];
#pragma unroll
        for (int jn = 0; jn < 8; ++jn) {
            mx0 = fmaxf(mx0, fmaxf(s[jn][0], s[jn][1]));
            mx1 = fmaxf(mx1, fmaxf(s[jn][2], s[jn][3]));
        }
        mx0 = fmaxf(mx0, __shfl_xor_sync(0xffffffffu, mx0, 1));
        mx0 = fmaxf(mx0, __shfl_xor_sync(0xffffffffu, mx0, 2));
        mx1 = fmaxf(mx1, __shfl_xor_sync(0xffffffffu, mx1, 1));
        mx1 = fmaxf(mx1, __shfl_xor_sync(0xffffffffu, mx1, 2));
        const float mn0 = fmaxf(mr0, mx0);
        const float mn1 = fmaxf(mr1, mx1);
        const float c0 = exp2p(mr0 - mn0);
        const float c1 = exp2p(mr1 - mn1);
        mr0 = mn0; mr1 = mn1;
        l0 *= c0; l1 *= c1;
#pragma unroll
        for (int jn = 0; jn < 8; ++jn) {
            s[jn][0] = exp2p(s[jn][0] - mr0);
            s[jn][1] = exp2p(s[jn][1] - mr0);
            s[jn][2] = exp2p(s[jn][2] - mr1);
            s[jn][3] = exp2p(s[jn][3] - mr1);
            l0 += s[jn][0] + s[jn][1];
            l1 += s[jn][2] + s[jn][3];
        }
#pragma unroll
        for (int jd = 0; jd < 8; ++jd) {
            o[jd][0] *= c0; o[jd][1] *= c0;
            o[jd][2] *= c1; o[jd][3] *= c1;
        }

#pragma unroll
        for (int q = 0; q < 4; ++q) {
            uint32_t a[4];
            a[0] = f2h2(s[2 * q][0], s[2 * q][1]);
            a[1] = f2h2(s[2 * q][2], s[2 * q][3]);
            a[2] = f2h2(s[2 * q + 1][0], s[2 * q + 1][1]);
            a[3] = f2h2(s[2 * q + 1][2], s[2 * q + 1][3]);
#pragma unroll
            for (int jd = 0; jd < 8; ++jd) {
                const uint32_t b0 = sVt[(q * 8 + lc) * 72 + jd * 8 + lr];
                const uint32_t b1 = sVt[(q * 8 + 4 + lc) * 72 + jd * 8 + lr];
                mma_f16(o[jd], a, b0, b1);
            }
        }
        __syncthreads();
        if (kb + 1 < 16) {
            storeRegs();
            __syncthreads();
        }
    }

    l0 += __shfl_xor_sync(0xffffffffu, l0, 1);
    l0 += __shfl_xor_sync(0xffffffffu, l0, 2);
    l1 += __shfl_xor_sync(0xffffffffu, l1, 1);
    l1 += __shfl_xor_sync(0xffffffffu, l1, 2);
    const float i0 = 1.f / l0;
    const float i1 = 1.f / l1;
    uint32_t* ow = reinterpret_cast<uint32_t*>(Oh);
    const size_t r0 = (size_t)(b * NS + q0 + wq + lr);
    const size_t r1 = r0 + 8;
#pragma unroll
    for (int jd = 0; jd < 8; ++jd) {
        ow[r0 * 512 + h * 32 + jd * 4 + lc] = f2h2(o[jd][0] * i0, o[jd][1] * i0);
        ow[r1 * 512 + h * 32 + jd * 4 + lc] = f2h2(o[jd][2] * i1, o[jd][3] * i1);
    }
}

// ---------------- residual add + LayerNorm (+ optional fused router gate) ----------
template<bool GATE>
__global__ __launch_bounds__(256) void add_ln_g(
    const float* __restrict__ A, const float* __restrict__ R,
    const float* __restrict__ g, const float* __restrict__ bt,
    float* __restrict__ out, __half* __restrict__ out16,
    const float* __restrict__ gw, const float* __restrict__ gb)
{
    const int t = blockIdx.x;
    const int tid = threadIdx.x;
    __shared__ float red[8];
    __shared__ float gl[8][8];

    const float4 a4 = *reinterpret_cast<const float4*>(A + (size_t)t * ND + tid * 4);
    const float4 r4 = *reinterpret_cast<const float4*>(R + (size_t)t * ND + tid * 4);
    float v[4] = {a4.x + r4.x, a4.y + r4.y, a4.z + r4.z, a4.w + r4.w};

    float sum = v[0] + v[1] + v[2] + v[3];
#pragma unroll
    for (int off = 16; off; off >>= 1) sum += __shfl_down_sync(0xffffffffu, sum, off);
    if ((tid & 31) == 0) red[tid >> 5] = sum;
    __syncthreads();
    if (tid < 8) {
        float s = red[tid];
#pragma unroll
        for (int off = 4; off; off >>= 1) s += __shfl_down_sync(0xffu, s, off);
        if (tid == 0) red[0] = s;
    }
    __syncthreads();
    const float mu = red[0] * (1.f / ND);
    __syncthreads();

    float vs = 0.f;
#pragma unroll
    for (int i = 0; i < 4; ++i) { float d = v[i] - mu; vs += d * d; }
#pragma unroll
    for (int off = 16; off; off >>= 1) vs += __shfl_down_sync(0xffffffffu, vs, off);
    if ((tid & 31) == 0) red[tid >> 5] = vs;
    __syncthreads();
    if (tid < 8) {
        float s = red[tid];
#pragma unroll
        for (int off = 4; off; off >>= 1) s += __shfl_down_sync(0xffu, s, off);
        if (tid == 0) red[0] = s;
    }
    __syncthreads();
    const float rstd = rsqrtf(red[0] * (1.f / ND) + EPS);

    float4 o4;
    const int d0 = tid * 4;
    o4.x = (v[0] - mu) * rstd * g[d0]     + bt[d0];
    o4.y = (v[1] - mu) * rstd * g[d0 + 1] + bt[d0 + 1];
    o4.z = (v[2] - mu) * rstd * g[d0 + 2] + bt[d0 + 2];
    o4.w = (v[3] - mu) * rstd * g[d0 + 3] + bt[d0 + 3];
    *reinterpret_cast<float4*>(out + (size_t)t * ND + d0) = o4;
    if (out16) {
        uint2 u;
        u.x = f2h2(o4.x, o4.y);
        u.y = f2h2(o4.z, o4.w);
        *reinterpret_cast<uint2*>(out16 + (size_t)t * ND + d0) = u;
    }

    if (GATE) {
        float ga[NE];
#pragma unroll
        for (int e = 0; e < NE; ++e) {
            const float4 w4 = *reinterpret_cast<const float4*>(gw + (size_t)e * ND + d0);
            ga[e] = o4.x * w4.x + o4.y * w4.y + o4.z * w4.z + o4.w * w4.w;
        }
#pragma unroll
        for (int e = 0; e < NE; ++e)
#pragma unroll
            for (int off = 16; off; off >>= 1)
                ga[e] += __shfl_down_sync(0xffffffffu, ga[e], off);
        if ((tid & 31) == 0) {
#pragma unroll
            for (int e = 0; e < NE; ++e) gl[tid >> 5][e] = ga[e];
        }
        __syncthreads();
        if (tid < NE) {
            float s = gb[tid];
#pragma unroll
            for (int w = 0; w < 8; ++w) s += gl[w][tid];
            gl[0][tid] = s;
        }
        __syncthreads();
        if (tid == 0) {
            int best = 0; float bv = gl[0][0];
#pragma unroll
            for (int e = 1; e < NE; ++e) {
                const float vv = gl[0][e];
                if (vv > bv) { bv = vv; best = e; }
            }
            g_idx[t] = best;
            atomicAdd(&g_cnt[best], 1);
        }
    }
}

// ---------------- routing ----------------
__global__ void route_init() {
    if (threadIdx.x < NE) g_cnt[threadIdx.x] = 0;
}

__global__ void route_scan() {
    g_off[0] = 0;
    for (int e = 0; e < NE; ++e) {
        g_off[e + 1] = g_off[e] + g_cnt[e];
        g_pos[e] = g_off[e];
    }
}

__global__ __launch_bounds__(256) void route_scatter() {
    const int t = blockIdx.x * 256 + threadIdx.x;
    if (t < NT) {
        const int e = g_idx[t];
        const int p = atomicAdd(&g_pos[e], 1);
        g_order[p] = t;
    }
}

// ---------------- launcher ----------------
extern "C" void kernel_launch(void* const* d_in, const int* in_sizes, int n_in,
                              void* d_out, int out_size)
{
    const float* x         = (const float*)d_in[0];
    const float* in_proj_w = (const float*)d_in[1];
    const float* in_proj_b = (const float*)d_in[2];
    const float* out_w     = (const float*)d_in[3];
    const float* out_b     = (const float*)d_in[4];
    const float* gate_w    = (const float*)d_in[5];
    const float* gate_b    = (const float*)d_in[6];
    const float* W1        = (const float*)d_in[7];
    const float* b1        = (const float*)d_in[8];
    const float* W2        = (const float*)d_in[9];
    const float* b2        = (const float*)d_in[10];
    const float* ln1_g     = (const float*)d_in[11];
    const float* ln1_b     = (const float*)d_in[12];
    const float* ln2_g     = (const float*)d_in[13];
    const float* ln2_b     = (const float*)d_in[14];
    float* out = (float*)d_out;

    __half *x16, *inwh, *outwh, *w1t, *w2t, *qkvh, *attnoh, *x1h, *hbuf;
    float  *tmp, *x1;
    cudaGetSymbolAddress((void**)&x16,    g_x16);
    cudaGetSymbolAddress((void**)&inwh,   g_inwh);
    cudaGetSymbolAddress((void**)&outwh,  g_outwh);
    cudaGetSymbolAddress((void**)&w1t,    g_w1t);
    cudaGetSymbolAddress((void**)&w2t,    g_w2t);
    cudaGetSymbolAddress((void**)&qkvh,   g_qkvh);
    cudaGetSymbolAddress((void**)&attnoh, g_attnoh);
    cudaGetSymbolAddress((void**)&x1h,    g_x1h);
    cudaGetSymbolAddress((void**)&hbuf,   g_h);
    cudaGetSymbolAddress((void**)&tmp,    g_tmp);
    cudaGetSymbolAddress((void**)&x1,     g_x1);

    cudaFuncSetAttribute(gemm_f16<0>, cudaFuncAttributeMaxDynamicSharedMemorySize, GEMM_SMEM_BYTES);
    cudaFuncSetAttribute(gemm_f16<1>, cudaFuncAttributeMaxDynamicSharedMemorySize, GEMM_SMEM_BYTES);
    cudaFuncSetAttribute(gemm_f16<2>, cudaFuncAttributeMaxDynamicSharedMemorySize, GEMM_SMEM_BYTES);
    cudaFuncSetAttribute(gemm_f16<3>, cudaFuncAttributeMaxDynamicSharedMemorySize, GEMM_SMEM_BYTES);

    // ---- side stream for the independent W1/W2 transposes (overlap with QKV/attn) ----
    cudaStream_t s2 = 0;
    cudaEvent_t evFork = 0, evJoin = 0;
    bool use2 =
        (cudaStreamCreateWithFlags(&s2, cudaStreamNonBlocking) == cudaSuccess) &&
        (cudaEventCreateWithFlags(&evFork, cudaEventDisableTiming) == cudaSuccess) &&
        (cudaEventCreateWithFlags(&evJoin, cudaEventDisableTiming) == cudaSuccess);

    route_init<<<1, 32>>>();

    if (use2) {
        cudaEventRecord(evFork, 0);
        cudaStreamWaitEvent(s2, evFork, 0);
        transpose_cvt<<<dim3(NF / 32, ND / 64, NE), 256, 0, s2>>>(W1, w1t, ND, NF);
        transpose_cvt<<<dim3(ND / 32, NF / 64, NE), 256, 0, s2>>>(W2, w2t, NF, ND);
        cudaEventRecord(evJoin, s2);
    } else {
        transpose_cvt<<<dim3(NF / 32, ND / 64, NE), 256>>>(W1, w1t, ND, NF);
        transpose_cvt<<<dim3(ND / 32, NF / 64, NE), 256>>>(W2, w2t, NF, ND);
    }

    // 0) conversions on the main stream
    cvt_f32_f16<<<NT * ND / 1024, 256>>>(x, x16, NT * ND / 4);
    cvt_f32_f16<<<3 * ND * ND / 1024, 256>>>(in_proj_w, inwh, 3 * ND * ND / 4);
    cvt_f32_f16<<<ND * ND / 1024, 256>>>(out_w, outwh, ND * ND / 4);

    // 1) QKV projection (fp16 out)
    gemm_f16<0><<<dim3(NT / 128, 3 * ND / 128, 1), 128, GEMM_SMEM_BYTES>>>(
        x16, ND, inwh, ND, in_proj_b, qkvh, 3 * ND, ND, 3 * ND);
    // 2) attention (fp16, register-prefetched K/V)
    flash_attn_f16<<<dim3(NS / 128, NB * NH), 256>>>(qkvh, attnoh);
    // 3) output projection (fp32 out)
    gemm_f16<1><<<dim3(NT / 128, ND / 128, 1), 128, GEMM_SMEM_BYTES>>>(
        attnoh, ND, outwh, ND, out_b, tmp, ND, ND, ND);
    // 4) residual + LN1 + fused router gate
    add_ln_g<true><<<NT, 256>>>(tmp, x, ln1_g, ln1_b, x1, x1h, gate_w, gate_b);
    // 5) routing finalize
    route_scan<<<1, 1>>>();
    route_scatter<<<NT / 256, 256>>>();
    // join the transpose branch before the MoE GEMMs consume w1t/w2t
    if (use2) cudaStreamWaitEvent(0, evJoin, 0);
    // 6) MoE expert FFN
    gemm_f16<2><<<dim3(NT / 128, NF / 128, NE), 128, GEMM_SMEM_BYTES>>>(
        x1h, ND, w1t, ND, b1, hbuf, NF, ND, NF);
    gemm_f16<3><<<dim3(NT / 128, ND / 128, NE), 128, GEMM_SMEM_BYTES>>>(
        hbuf, NF, w2t, NF, b2, tmp, ND, NF, ND);
    // 7) residual + LN2 -> output
    add_ln_g<false><<<NT, 256>>>(tmp, x1, ln2_g, ln2_b, out, nullptr, nullptr, nullptr);

    (void)in_sizes; (void)n_in; (void)out_size;
}

// round 15
// speedup vs baseline: 1.0085x; 1.0085x over previous
#include <cuda_runtime.h>
#include <cuda_fp16.h>
#include <math.h>
#include <float.h>
#include <stdint.h>

// ---------------- problem constants ----------------
constexpr int NB  = 4;
constexpr int NS  = 1024;
constexpr int ND  = 1024;
constexpr int NH  = 16;
constexpr int NHD = 64;
constexpr int NE  = 8;
constexpr int NF  = 4096;
constexpr int NT  = NB * NS;            // 4096 tokens
constexpr float EPS = 1e-5f;

// fused conversion segment sizes (float4 units)
constexpr int NX4  = NT * ND / 4;           // 1,048,576
constexpr int NWI4 = 3 * ND * ND / 4;       //   786,432
constexpr int NWO4 = ND * ND / 4;           //   262,144
constexpr int NTOT4 = NX4 + NWI4 + NWO4;    // 2,097,152

// ---------------- scratch (device globals; no runtime alloc) ----------------
__device__ __half g_x16[(size_t)NT * ND];
__device__ __half g_inwh[(size_t)3 * ND * ND];
__device__ __half g_outwh[(size_t)ND * ND];
__device__ __half g_w1t[(size_t)NE * NF * ND];      // [E][F][D] fp16 (transposed)
__device__ __half g_w2t[(size_t)NE * ND * NF];      // [E][D][F] fp16 (transposed)
__device__ __half g_qkvh[(size_t)NT * 3 * ND];
__device__ __half g_attnoh[(size_t)NT * ND];
__device__ __half g_x1h[(size_t)NT * ND];
__device__ __half g_h[(size_t)(NT + 128) * NF];     // fp16 hidden
__device__ float  g_tmp[(size_t)NT * ND];
__device__ float  g_x1[(size_t)NT * ND];
__device__ int    g_idx[NT];
__device__ int    g_order[NT];
__device__ int    g_cnt[NE];
__device__ int    g_off[NE + 1];
__device__ int    g_pos[NE];

// ---------------- helpers ----------------
__device__ __forceinline__ uint32_t f2h2(float lo, float hi) {
    __half2 h = __floats2half2_rn(lo, hi);
    return *reinterpret_cast<uint32_t*>(&h);
}
__device__ __forceinline__ uint32_t smem_u32(const void* p) {
    uint32_t a;
    asm("{ .reg .u64 t; cvta.to.shared.u64 t, %1; cvt.u32.u64 %0, t; }" : "=r"(a) : "l"(p));
    return a;
}
__device__ __forceinline__ void mma_f16(float c[4], const uint32_t a[4],
                                        uint32_t b0, uint32_t b1) {
    asm volatile(
        "mma.sync.aligned.m16n8k16.row.col.f32.f16.f16.f32 "
        "{%0,%1,%2,%3}, {%4,%5,%6,%7}, {%8,%9}, {%0,%1,%2,%3};"
        : "+f"(c[0]), "+f"(c[1]), "+f"(c[2]), "+f"(c[3])
        : "r"(a[0]), "r"(a[1]), "r"(a[2]), "r"(a[3]), "r"(b0), "r"(b1));
}
__device__ __forceinline__ void ldsm_x4(uint32_t d[4], uint32_t addr) {
    asm volatile("ldmatrix.sync.aligned.m8n8.x4.shared.b16 {%0,%1,%2,%3}, [%4];"
                 : "=r"(d[0]), "=r"(d[1]), "=r"(d[2]), "=r"(d[3]) : "r"(addr));
}
__device__ __forceinline__ void cpa16(uint32_t saddr, const void* gptr, bool valid) {
    const int sz = valid ? 16 : 0;
    asm volatile("cp.async.cg.shared.global [%0], [%1], 16, %2;"
                 :: "r"(saddr), "l"(gptr), "r"(sz));
}
#define CP_COMMIT()  asm volatile("cp.async.commit_group;")
#define CP_WAIT2()   asm volatile("cp.async.wait_group 2;")

// fast 2^y for y <= 0, FMA pipe only. |rel err| ~3e-6.
__device__ __forceinline__ float exp2p(float y) {
    y = fmaxf(y, -80.f);
    const int ni = __float2int_rn(y);
    const float f = y - (float)ni;
    float p = 0.0013333558146428443f;
    p = fmaf(p, f, 0.009618129107628477f);
    p = fmaf(p, f, 0.05550410866482158f);
    p = fmaf(p, f, 0.2402265069591007f);
    p = fmaf(p, f, 0.6931471805599453f);
    p = fmaf(p, f, 1.0f);
    return __uint_as_float(__float_as_uint(p) + ((uint32_t)ni << 23));
}

// ---------------- fused conversion kernel (x, in_proj_w, out_w -> fp16) ----------
__global__ __launch_bounds__(256) void cvt_all(
    const float* __restrict__ x, const float* __restrict__ wi,
    const float* __restrict__ wo,
    __half* __restrict__ dx, __half* __restrict__ dwi, __half* __restrict__ dwo)
{
    const int stride = gridDim.x * 256;
    for (int i = blockIdx.x * 256 + threadIdx.x; i < NTOT4; i += stride) {
        const float4* s;
        uint2* d;
        int j;
        if (i < NX4) {
            s = reinterpret_cast<const float4*>(x);   d = reinterpret_cast<uint2*>(dx);   j = i;
        } else if (i < NX4 + NWI4) {
            s = reinterpret_cast<const float4*>(wi);  d = reinterpret_cast<uint2*>(dwi);  j = i - NX4;
        } else {
            s = reinterpret_cast<const float4*>(wo);  d = reinterpret_cast<uint2*>(dwo);  j = i - NX4 - NWI4;
        }
        const float4 v = s[j];
        uint2 u;
        u.x = f2h2(v.x, v.y);
        u.y = f2h2(v.z, v.w);
        d[j] = u;
    }
}

// transpose + convert: src [Kd][Nd] fp32 -> dst [Nd][Kd] fp16, per expert (blockIdx.z)
__global__ __launch_bounds__(256) void transpose_cvt(
    const float* __restrict__ src, __half* __restrict__ dst, int Kd, int Nd)
{
    __shared__ float t[64][33];
    const size_t eofs = (size_t)blockIdx.z * (size_t)Kd * Nd;
    const int n0 = blockIdx.x * 32;
    const int k0 = blockIdx.y * 64;
    const int tx = threadIdx.x & 31;
    const int ty = threadIdx.x >> 5;   // 0..7
#pragma unroll
    for (int i = 0; i < 8; ++i)
        t[ty + i * 8][tx] = src[eofs + (size_t)(k0 + ty + i * 8) * Nd + n0 + tx];
    __syncthreads();
    const int nl = threadIdx.x >> 3;   // 0..31
    const int kc = threadIdx.x & 7;    // 0..7
    __half* drow = dst + eofs + (size_t)(n0 + nl) * Kd + k0;
#pragma unroll
    for (int j = 0; j < 4; ++j) {
        const int k2 = kc + j * 8;     // half2 index 0..31
        __half2 h = __floats2half2_rn(t[2 * k2][nl], t[2 * k2 + 1][nl]);
        *reinterpret_cast<__half2*>(drow + 2 * k2) = h;
    }
}

// ================= fp16 GEMM: 4 warps x (64x64), cp.async 4-stage, ldmatrix ========
// (BK=32, 4 stages, 3 in flight — the 534-us configuration)
constexpr int G_ASTG = 2560;                 // [128][20] words per stage
constexpr int G_BOFF = 4 * G_ASTG;           // 10240
constexpr int GEMM_SMEM_BYTES = 8 * G_ASTG * 4;   // 81920 B

template<int MODE>
__global__ void __launch_bounds__(128, 2) gemm_f16(
    const __half* __restrict__ A, int lda,
    const __half* __restrict__ B, int ldb,
    const float* __restrict__ bias,
    void* __restrict__ Cv, int ldc,
    int K, int Nglob)
{
    extern __shared__ uint32_t smw[];
    __shared__ int tok[128];

    const int tid = threadIdx.x;
    const int wid = tid >> 5;           // 0..3
    const int ln  = tid & 31;
    const int wm  = wid >> 1;           // 0..1 -> 64-row slice
    const int wn  = wid & 1;            // 0..1 -> 64-col slice
    const int m0 = blockIdx.x * 128;
    const int n0 = blockIdx.y * 128;

    int seg0 = 0, seg1 = 1 << 30;
    const __half* Bp = B;
    const float* biasp = bias;
    if (MODE >= 2) {
        const int e = blockIdx.z;
        seg0 = g_off[e]; seg1 = g_off[e + 1];
        if (seg0 + m0 >= seg1) return;
        Bp    = B + (size_t)e * K * Nglob;
        biasp = bias + (size_t)e * Nglob;
        {
            const int p = seg0 + m0 + tid;
            tok[tid] = (p < seg1) ? g_order[p] : -1;
        }
        __syncthreads();
    }

    const uint32_t sbase = smem_u32(smw);

    const uint32_t aoff0 = ((uint32_t)(wm * 64 + (ln & 15)) * 20u + (uint32_t)(ln >> 4) * 4u) * 4u;
    const uint32_t brow = (uint32_t)(wn * 64) + (uint32_t)(((ln >> 4) << 3) | (ln & 7));
    const uint32_t boff0 = (brow * 20u + (uint32_t)((ln >> 3) & 1) * 4u) * 4u;

    float acc[4][8][4];
#pragma unroll
    for (int mt = 0; mt < 4; ++mt)
#pragma unroll
        for (int nt = 0; nt < 8; ++nt)
#pragma unroll
            for (int r = 0; r < 4; ++r) acc[mt][nt][r] = 0.f;

    const int nK = K >> 5;

    auto issue = [&](int kt) {
        const int k0 = kt << 5;
        const int s = kt & 3;
        const uint32_t sA = sbase + (s * G_ASTG) * 4;
        const uint32_t sB = sbase + (G_BOFF + s * G_ASTG) * 4;
#pragma unroll
        for (int it = 0; it < 4; ++it) {
            const int idx = tid + it * 128;   // 0..511
            const int row = idx >> 2;         // 0..127
            const int c   = idx & 3;          // 16B chunk
            const __half* ga;
            bool vA = true;
            if (MODE == 2) {
                const int tk = tok[row];
                vA = (tk >= 0);
                ga = A + (size_t)(vA ? tk : 0) * lda + k0 + c * 8;
            } else if (MODE == 3) {
                ga = A + (size_t)(seg0 + m0 + row) * lda + k0 + c * 8;
            } else {
                ga = A + (size_t)(m0 + row) * lda + k0 + c * 8;
            }
            cpa16(sA + (row * 20 + c * 4) * 4, ga, vA);
            const __half* gb = Bp + (size_t)(n0 + row) * ldb + k0 + c * 8;
            cpa16(sB + (row * 20 + c * 4) * 4, gb, true);
        }
    };
    auto compute = [&](int kt) {
        const int s = kt & 3;
        const uint32_t aab = sbase + (s * G_ASTG) * 4 + aoff0;
        const uint32_t bab = sbase + ((G_BOFF + s * G_ASTG)) * 4 + boff0;
#pragma unroll
        for (int ks = 0; ks < 2; ++ks) {
            const uint32_t kofs = (uint32_t)ks * 32u;
            uint32_t af[4][4];
#pragma unroll
            for (int mt = 0; mt < 4; ++mt)
                ldsm_x4(af[mt], aab + (uint32_t)mt * 1280u + kofs);
#pragma unroll
            for (int q = 0; q < 4; ++q) {
                uint32_t bf[4];
                ldsm_x4(bf, bab + (uint32_t)q * 1280u + kofs);
#pragma unroll
                for (int mt = 0; mt < 4; ++mt) {
                    mma_f16(acc[mt][2 * q],     af[mt], bf[0], bf[1]);
                    mma_f16(acc[mt][2 * q + 1], af[mt], bf[2], bf[3]);
                }
            }
        }
    };

    issue(0); CP_COMMIT();
    issue(1); CP_COMMIT();
    issue(2); CP_COMMIT();
    for (int kt = 0; kt < nK; ++kt) {
        CP_WAIT2();
        __syncthreads();
        if (kt + 3 < nK) issue(kt + 3);
        CP_COMMIT();
        compute(kt);
    }

    const int lr = ln >> 2;
    const int lc = ln & 3;
#pragma unroll
    for (int mt = 0; mt < 4; ++mt) {
#pragma unroll
        for (int half = 0; half < 2; ++half) {
            const int lrow = wm * 64 + mt * 16 + half * 8 + lr;
            bool valid = true;
            size_t rowidx = 0;
            if (MODE == 0 || MODE == 1) {
                rowidx = (size_t)(m0 + lrow);
            } else if (MODE == 2) {
                const int p = seg0 + m0 + lrow;
                valid = (p < seg1);
                rowidx = (size_t)p;
            } else {
                const int tk = tok[lrow];
                valid = (tk >= 0);
                rowidx = (size_t)(valid ? tk : 0);
            }
            if (!valid) continue;
#pragma unroll
            for (int nt = 0; nt < 8; ++nt) {
                const int cc = n0 + wn * 64 + nt * 8 + lc * 2;
                float vx = acc[mt][nt][half * 2 + 0] + biasp[cc];
                float vy = acc[mt][nt][half * 2 + 1] + biasp[cc + 1];
                if (MODE == 0) {
                    uint32_t* dst = (uint32_t*)Cv + rowidx * (ldc >> 1) + (cc >> 1);
                    *dst = f2h2(vx, vy);
                } else if (MODE == 2) {
                    vx = fmaxf(vx, 0.f); vy = fmaxf(vy, 0.f);
                    uint32_t* dst = (uint32_t*)Cv + rowidx * (ldc >> 1) + (cc >> 1);
                    *dst = f2h2(vx, vy);
                } else {
                    float2 v; v.x = vx; v.y = vy;
                    *reinterpret_cast<float2*>((float*)Cv + rowidx * ldc + cc) = v;
                }
            }
        }
    }
}

// ================= fp16 flash attention with register-prefetched K/V =================
__global__ void __launch_bounds__(256, 2) flash_attn_f16(
    const __half* __restrict__ qkvh, __half* __restrict__ Oh)
{
    __shared__ uint32_t sQ[128 * 36];
    __shared__ uint32_t sK[64 * 36];
    __shared__ uint32_t sVt[32 * 72];

    const int tid = threadIdx.x;
    const int wid = tid >> 5;
    const int ln  = tid & 31;
    const int lr  = ln >> 2;
    const int lc  = ln & 3;
    const int b   = blockIdx.y >> 4;
    const int h   = blockIdx.y & 15;
    const int q0  = blockIdx.x * 128;
    const int wq  = wid * 16;
    const float qscale = 0.18033688011112042f;   // log2(e) / sqrt(64)

    const uint32_t* qkw = reinterpret_cast<const uint32_t*>(qkvh);   // 1536 words/row

#pragma unroll
    for (int it = 0; it < 4; ++it) {
        const int idx = tid + it * 256;
        const int row = idx >> 3;
        const int c   = idx & 7;
        const uint32_t* src = qkw + (size_t)(b * NS + q0 + row) * 1536 + h * 32 + c * 4;
        *reinterpret_cast<uint4*>(&sQ[row * 36 + c * 4]) = *reinterpret_cast<const uint4*>(src);
    }

    uint4 pk[2];
    uint4 pvlo, pvhi;
    const int krow0 = tid >> 3;
    const int kc0   = tid & 7;
    const int vk2   = tid >> 3;
    const int vdc   = tid & 7;

    auto loadRegs = [&](int kb) {
#pragma unroll
        for (int it = 0; it < 2; ++it) {
            const int row = krow0 + it * 32;
            const uint32_t* src = qkw + (size_t)(b * NS + kb * 64 + row) * 1536 + 512 + h * 32 + kc0 * 4;
            pk[it] = *reinterpret_cast<const uint4*>(src);
        }
        const uint32_t* vb = qkw + (size_t)(b * NS + kb * 64 + 2 * vk2) * 1536 + 1024 + h * 32 + vdc * 4;
        pvlo = *reinterpret_cast<const uint4*>(vb);
        pvhi = *reinterpret_cast<const uint4*>(vb + 1536);
    };
    auto storeRegs = [&]() {
#pragma unroll
        for (int it = 0; it < 2; ++it) {
            const int row = krow0 + it * 32;
            *reinterpret_cast<uint4*>(&sK[row * 36 + kc0 * 4]) = pk[it];
        }
        uint4 w0, w1;
        w0.x = __byte_perm(pvlo.x, pvhi.x, 0x5410); w0.y = __byte_perm(pvlo.x, pvhi.x, 0x7632);
        w0.z = __byte_perm(pvlo.y, pvhi.y, 0x5410); w0.w = __byte_perm(pvlo.y, pvhi.y, 0x7632);
        w1.x = __byte_perm(pvlo.z, pvhi.z, 0x5410); w1.y = __byte_perm(pvlo.z, pvhi.z, 0x7632);
        w1.z = __byte_perm(pvlo.w, pvhi.w, 0x5410); w1.w = __byte_perm(pvlo.w, pvhi.w, 0x7632);
        *reinterpret_cast<uint4*>(&sVt[vk2 * 72 + vdc * 8]) = w0;
        *reinterpret_cast<uint4*>(&sVt[vk2 * 72 + vdc * 8 + 4]) = w1;
    };

    float mr0 = -1e30f, mr1 = -1e30f;
    float l0 = 0.f, l1 = 0.f;
    float o[8][4];
#pragma unroll
    for (int jd = 0; jd < 8; ++jd)
#pragma unroll
        for (int r = 0; r < 4; ++r) o[jd][r] = 0.f;

    loadRegs(0);
    storeRegs();
    __syncthreads();

    for (int kb = 0; kb < 16; ++kb) {
        if (kb + 1 < 16) loadRegs(kb + 1);

        float s[8][4];
#pragma unroll
        for (int jn = 0; jn < 8; ++jn)
#pragma unroll
            for (int r = 0; r < 4; ++r) s[jn][r] = 0.f;
#pragma unroll
        for (int kk = 0; kk < 4; ++kk) {
            uint32_t a[4];
            a[0] = sQ[(wq + lr) * 36 + kk * 8 + lc];
            a[1] = sQ[(wq + lr + 8) * 36 + kk * 8 + lc];
            a[2] = sQ[(wq + lr) * 36 + kk * 8 + 4 + lc];
            a[3] = sQ[(wq + lr + 8) * 36 + kk * 8 + 4 + lc];
#pragma unroll
            for (int jn = 0; jn < 8; ++jn) {
                const uint32_t b0 = sK[(jn * 8 + lr) * 36 + kk * 8 + lc];
                const uint32_t b1 = sK[(jn * 8 + lr) * 36 + kk * 8 + 4 + lc];
                mma_f16(s[jn], a, b0, b1);
            }
        }
#pragma unroll
        for (int jn = 0; jn < 8; ++jn)
#pragma unroll
            for (int r = 0; r < 4; ++r) s[jn][r] *= qscale;

        float mx0 = s[0][0], mx1 = s[0][2];
#pragma unroll
        for (int jn = 0; jn < 8; ++jn) {
            mx0 = fmaxf(mx0, fmaxf(s[jn][0], s[jn][1]));
            mx1 = fmaxf(mx1, fmaxf(s[jn][2], s[jn][3]));
        }
        mx0 = fmaxf(mx0, __shfl_xor_sync(0xffffffffu, mx0, 1));
        mx0 = fmaxf(mx0, __shfl_xor_sync(0xffffffffu, mx0, 2));
        mx1 = fmaxf(mx1, __shfl_xor_sync(0xffffffffu, mx1, 1));
        mx1 = fmaxf(mx1, __shfl_xor_sync(0xffffffffu, mx1, 2));
        const float mn0 = fmaxf(mr0, mx0);
        const float mn1 = fmaxf(mr1, mx1);
        const float c0 = exp2p(mr0 - mn0);
        const float c1 = exp2p(mr1 - mn1);
        mr0 = mn0; mr1 = mn1;
        l0 *= c0; l1 *= c1;
#pragma unroll
        for (int jn = 0; jn < 8; ++jn) {
            s[jn][0] = exp2p(s[jn][0] - mr0);
            s[jn][1] = exp2p(s[jn][1] - mr0);
            s[jn][2] = exp2p(s[jn][2] - mr1);
            s[jn][3] = exp2p(s[jn][3] - mr1);
            l0 += s[jn][0] + s[jn][1];
            l1 += s[jn][2] + s[jn][3];
        }
#pragma unroll
        for (int jd = 0; jd < 8; ++jd) {
            o[jd][0] *= c0; o[jd][1] *= c0;
            o[jd][2] *= c1; o[jd][3] *= c1;
        }

#pragma unroll
        for (int q = 0; q < 4; ++q) {
            uint32_t a[4];
            a[0] = f2h2(s[2 * q][0], s[2 * q][1]);
            a[1] = f2h2(s[2 * q][2], s[2 * q][3]);
            a[2] = f2h2(s[2 * q + 1][0], s[2 * q + 1][1]);
            a[3] = f2h2(s[2 * q + 1][2], s[2 * q + 1][3]);
#pragma unroll
            for (int jd = 0; jd < 8; ++jd) {
                const uint32_t b0 = sVt[(q * 8 + lc) * 72 + jd * 8 + lr];
                const uint32_t b1 = sVt[(q * 8 + 4 + lc) * 72 + jd * 8 + lr];
                mma_f16(o[jd], a, b0, b1);
            }
        }
        __syncthreads();
        if (kb + 1 < 16) {
            storeRegs();
            __syncthreads();
        }
    }

    l0 += __shfl_xor_sync(0xffffffffu, l0, 1);
    l0 += __shfl_xor_sync(0xffffffffu, l0, 2);
    l1 += __shfl_xor_sync(0xffffffffu, l1, 1);
    l1 += __shfl_xor_sync(0xffffffffu, l1, 2);
    const float i0 = 1.f / l0;
    const float i1 = 1.f / l1;
    uint32_t* ow = reinterpret_cast<uint32_t*>(Oh);
    const size_t r0 = (size_t)(b * NS + q0 + wq + lr);
    const size_t r1 = r0 + 8;
#pragma unroll
    for (int jd = 0; jd < 8; ++jd) {
        ow[r0 * 512 + h * 32 + jd * 4 + lc] = f2h2(o[jd][0] * i0, o[jd][1] * i0);
        ow[r1 * 512 + h * 32 + jd * 4 + lc] = f2h2(o[jd][2] * i1, o[jd][3] * i1);
    }
}

// ---------------- residual add + LayerNorm (+ optional fused router gate) ----------
template<bool GATE>
__global__ __launch_bounds__(256) void add_ln_g(
    const float* __restrict__ A, const float* __restrict__ R,
    const float* __restrict__ g, const float* __restrict__ bt,
    float* __restrict__ out, __half* __restrict__ out16,
    const float* __restrict__ gw, const float* __restrict__ gb)
{
    const int t = blockIdx.x;
    const int tid = threadIdx.x;
    __shared__ float red[8];
    __shared__ float gl[8][8];

    const float4 a4 = *reinterpret_cast<const float4*>(A + (size_t)t * ND + tid * 4);
    const float4 r4 = *reinterpret_cast<const float4*>(R + (size_t)t * ND + tid * 4);
    float v[4] = {a4.x + r4.x, a4.y + r4.y, a4.z + r4.z, a4.w + r4.w};

    float sum = v[0] + v[1] + v[2] + v[3];
#pragma unroll
    for (int off = 16; off; off >>= 1) sum += __shfl_down_sync(0xffffffffu, sum, off);
    if ((tid & 31) == 0) red[tid >> 5] = sum;
    __syncthreads();
    if (tid < 8) {
        float s = red[tid];
#pragma unroll
        for (int off = 4; off; off >>= 1) s += __shfl_down_sync(0xffu, s, off);
        if (tid == 0) red[0] = s;
    }
    __syncthreads();
    const float mu = red[0] * (1.f / ND);
    __syncthreads();

    float vs = 0.f;
#pragma unroll
    for (int i = 0; i < 4; ++i) { float d = v[i] - mu; vs += d * d; }
#pragma unroll
    for (int off = 16; off; off >>= 1) vs += __shfl_down_sync(0xffffffffu, vs, off);
    if ((tid & 31) == 0) red[tid >> 5] = vs;
    __syncthreads();
    if (tid < 8) {
        float s = red[tid];
#pragma unroll
        for (int off = 4; off; off >>= 1) s += __shfl_down_sync(0xffu, s, off);
        if (tid == 0) red[0] = s;
    }
    __syncthreads();
    const float rstd = rsqrtf(red[0] * (1.f / ND) + EPS);

    float4 o4;
    const int d0 = tid * 4;
    o4.x = (v[0] - mu) * rstd * g[d0]     + bt[d0];
    o4.y = (v[1] - mu) * rstd * g[d0 + 1] + bt[d0 + 1];
    o4.z = (v[2] - mu) * rstd * g[d0 + 2] + bt[d0 + 2];
    o4.w = (v[3] - mu) * rstd * g[d0 + 3] + bt[d0 + 3];
    *reinterpret_cast<float4*>(out + (size_t)t * ND + d0) = o4;
    if (out16) {
        uint2 u;
        u.x = f2h2(o4.x, o4.y);
        u.y = f2h2(o4.z, o4.w);
        *reinterpret_cast<uint2*>(out16 + (size_t)t * ND + d0) = u;
    }

    if (GATE) {
        float ga[NE];
#pragma unroll
        for (int e = 0; e < NE; ++e) {
            const float4 w4 = *reinterpret_cast<const float4*>(gw + (size_t)e * ND + d0);
            ga[e] = o4.x * w4.x + o4.y * w4.y + o4.z * w4.z + o4.w * w4.w;
        }
#pragma unroll
        for (int e = 0; e < NE; ++e)
#pragma unroll
            for (int off = 16; off; off >>= 1)
                ga[e] += __shfl_down_sync(0xffffffffu, ga[e], off);
        if ((tid & 31) == 0) {
#pragma unroll
            for (int e = 0; e < NE; ++e) gl[tid >> 5][e] = ga[e];
        }
        __syncthreads();
        if (tid < NE) {
            float s = gb[tid];
#pragma unroll
            for (int w = 0; w < 8; ++w) s += gl[w][tid];
            gl[0][tid] = s;
        }
        __syncthreads();
        if (tid == 0) {
            int best = 0; float bv = gl[0][0];
#pragma unroll
            for (int e = 1; e < NE; ++e) {
                const float vv = gl[0][e];
                if (vv > bv) { bv = vv; best = e; }
            }
            g_idx[t] = best;
            atomicAdd(&g_cnt[best], 1);
        }
    }
}

// ---------------- routing ----------------
__global__ void route_init() {
    if (threadIdx.x < NE) g_cnt[threadIdx.x] = 0;
}

__global__ void route_scan() {
    g_off[0] = 0;
    for (int e = 0; e < NE; ++e) {
        g_off[e + 1] = g_off[e] + g_cnt[e];
        g_pos[e] = g_off[e];
    }
}

__global__ __launch_bounds__(256) void route_scatter() {
    const int t = blockIdx.x * 256 + threadIdx.x;
    if (t < NT) {
        const int e = g_idx[t];
        const int p = atomicAdd(&g_pos[e], 1);
        g_order[p] = t;
    }
}

// ---------------- launcher ----------------
extern "C" void kernel_launch(void* const* d_in, const int* in_sizes, int n_in,
                              void* d_out, int out_size)
{
    const float* x         = (const float*)d_in[0];
    const float* in_proj_w = (const float*)d_in[1];
    const float* in_proj_b = (const float*)d_in[2];
    const float* out_w     = (const float*)d_in[3];
    const float* out_b     = (const float*)d_in[4];
    const float* gate_w    = (const float*)d_in[5];
    const float* gate_b    = (const float*)d_in[6];
    const float* W1        = (const float*)d_in[7];
    const float* b1        = (const float*)d_in[8];
    const float* W2        = (const float*)d_in[9];
    const float* b2        = (const float*)d_in[10];
    const float* ln1_g     = (const float*)d_in[11];
    const float* ln1_b     = (const float*)d_in[12];
    const float* ln2_g     = (const float*)d_in[13];
    const float* ln2_b     = (const float*)d_in[14];
    float* out = (float*)d_out;

    __half *x16, *inwh, *outwh, *w1t, *w2t, *qkvh, *attnoh, *x1h, *hbuf;
    float  *tmp, *x1;
    cudaGetSymbolAddress((void**)&x16,    g_x16);
    cudaGetSymbolAddress((void**)&inwh,   g_inwh);
    cudaGetSymbolAddress((void**)&outwh,  g_outwh);
    cudaGetSymbolAddress((void**)&w1t,    g_w1t);
    cudaGetSymbolAddress((void**)&w2t,    g_w2t);
    cudaGetSymbolAddress((void**)&qkvh,   g_qkvh);
    cudaGetSymbolAddress((void**)&attnoh, g_attnoh);
    cudaGetSymbolAddress((void**)&x1h,    g_x1h);
    cudaGetSymbolAddress((void**)&hbuf,   g_h);
    cudaGetSymbolAddress((void**)&tmp,    g_tmp);
    cudaGetSymbolAddress((void**)&x1,     g_x1);

    cudaFuncSetAttribute(gemm_f16<0>, cudaFuncAttributeMaxDynamicSharedMemorySize, GEMM_SMEM_BYTES);
    cudaFuncSetAttribute(gemm_f16<1>, cudaFuncAttributeMaxDynamicSharedMemorySize, GEMM_SMEM_BYTES);
    cudaFuncSetAttribute(gemm_f16<2>, cudaFuncAttributeMaxDynamicSharedMemorySize, GEMM_SMEM_BYTES);
    cudaFuncSetAttribute(gemm_f16<3>, cudaFuncAttributeMaxDynamicSharedMemorySize, GEMM_SMEM_BYTES);

    // ---- side stream for the independent W1/W2 transposes (overlap with QKV/attn) ----
    cudaStream_t s2 = 0;
    cudaEvent_t evFork = 0, evJoin = 0;
    bool use2 =
        (cudaStreamCreateWithFlags(&s2, cudaStreamNonBlocking) == cudaSuccess) &&
        (cudaEventCreateWithFlags(&evFork, cudaEventDisableTiming) == cudaSuccess) &&
        (cudaEventCreateWithFlags(&evJoin, cudaEventDisableTiming) == cudaSuccess);

    route_init<<<1, 32>>>();

    if (use2) {
        cudaEventRecord(evFork, 0);
        cudaStreamWaitEvent(s2, evFork, 0);
        transpose_cvt<<<dim3(NF / 32, ND / 64, NE), 256, 0, s2>>>(W1, w1t, ND, NF);
        transpose_cvt<<<dim3(ND / 32, NF / 64, NE), 256, 0, s2>>>(W2, w2t, NF, ND);
        cudaEventRecord(evJoin, s2);
    } else {
        transpose_cvt<<<dim3(NF / 32, ND / 64, NE), 256>>>(W1, w1t, ND, NF);
        transpose_cvt<<<dim3(ND / 32, NF / 64, NE), 256>>>(W2, w2t, NF, ND);
    }

    // 0) fused conversion (x, in_proj_w, out_w) on the main stream
    cvt_all<<<1024, 256>>>(x, in_proj_w, out_w, x16, inwh, outwh);

    // 1) QKV projection (fp16 out)
    gemm_f16<0><<<dim3(NT / 128, 3 * ND / 128, 1), 128, GEMM_SMEM_BYTES>>>(
        x16, ND, inwh, ND, in_proj_b, qkvh, 3 * ND, ND, 3 * ND);
    // 2) attention (fp16, register-prefetched K/V)
    flash_attn_f16<<<dim3(NS / 128, NB * NH), 256>>>(qkvh, attnoh);
    // 3) output projection (fp32 out)
    gemm_f16<1><<<dim3(NT / 128, ND / 128, 1), 128, GEMM_SMEM_BYTES>>>(
        attnoh, ND, outwh, ND, out_b, tmp, ND, ND, ND);
    // 4) residual + LN1 + fused router gate
    add_ln_g<true><<<NT, 256>>>(tmp, x, ln1_g, ln1_b, x1, x1h, gate_w, gate_b);
    // 5) routing finalize
    route_scan<<<1, 1>>>();
    route_scatter<<<NT / 256, 256>>>();
    // join the transpose branch before the MoE GEMMs consume w1t/w2t
    if (use2) cudaStreamWaitEvent(0, evJoin, 0);
    // 6) MoE expert FFN
    gemm_f16<2><<<dim3(NT / 128, NF / 128, NE), 128, GEMM_SMEM_BYTES>>>(
        x1h, ND, w1t, ND, b1, hbuf, NF, ND, NF);
    gemm_f16<3><<<dim3(NT / 128, ND / 128, NE), 128, GEMM_SMEM_BYTES>>>(
        hbuf, NF, w2t, NF, b2, tmp, ND, NF, ND);
    // 7) residual + LN2 -> output
    add_ln_g<false><<<NT, 256>>>(tmp, x1, ln2_g, ln2_b, out, nullptr, nullptr, nullptr);

    (void)in_sizes; (void)n_in; (void)out_size;
}

// round 16
// speedup vs baseline: 1.0468x; 1.0379x over previous
#include <cuda_runtime.h>
#include <cuda_fp16.h>
#include <math.h>
#include <float.h>
#include <stdint.h>

// ---------------- problem constants ----------------
constexpr int NB  = 4;
constexpr int NS  = 1024;
constexpr int ND  = 1024;
constexpr int NH  = 16;
constexpr int NHD = 64;
constexpr int NE  = 8;
constexpr int NF  = 4096;
constexpr int NT  = NB * NS;            // 4096 tokens
constexpr float EPS = 1e-5f;

// fused conversion segment sizes (float4 units): x + in_proj_w only
constexpr int NX4  = NT * ND / 4;           // 1,048,576
constexpr int NWI4 = 3 * ND * ND / 4;       //   786,432
constexpr int NTOT4 = NX4 + NWI4;           // 1,835,008

// ---------------- scratch (device globals; no runtime alloc) ----------------
__device__ __half g_x16[(size_t)NT * ND];
__device__ __half g_inwh[(size_t)3 * ND * ND];
__device__ __half g_outwh[(size_t)ND * ND];
__device__ __half g_w1t[(size_t)NE * NF * ND];      // [E][F][D] fp16 (transposed)
__device__ __half g_w2t[(size_t)NE * ND * NF];      // [E][D][F] fp16 (transposed)
__device__ __half g_qkvh[(size_t)NT * 3 * ND];
__device__ __half g_attnoh[(size_t)NT * ND];
__device__ __half g_x1h[(size_t)NT * ND];
__device__ __half g_h[(size_t)(NT + 128) * NF];     // fp16 hidden
__device__ float  g_tmp[(size_t)NT * ND];
__device__ float  g_x1[(size_t)NT * ND];
__device__ int    g_idx[NT];
__device__ int    g_order[NT];
__device__ int    g_cnt[NE];
__device__ int    g_pos[NE];

// ---------------- helpers ----------------
__device__ __forceinline__ uint32_t f2h2(float lo, float hi) {
    __half2 h = __floats2half2_rn(lo, hi);
    return *reinterpret_cast<uint32_t*>(&h);
}
__device__ __forceinline__ uint32_t smem_u32(const void* p) {
    uint32_t a;
    asm("{ .reg .u64 t; cvta.to.shared.u64 t, %1; cvt.u32.u64 %0, t; }" : "=r"(a) : "l"(p));
    return a;
}
__device__ __forceinline__ void mma_f16(float c[4], const uint32_t a[4],
                                        uint32_t b0, uint32_t b1) {
    asm volatile(
        "mma.sync.aligned.m16n8k16.row.col.f32.f16.f16.f32 "
        "{%0,%1,%2,%3}, {%4,%5,%6,%7}, {%8,%9}, {%0,%1,%2,%3};"
        : "+f"(c[0]), "+f"(c[1]), "+f"(c[2]), "+f"(c[3])
        : "r"(a[0]), "r"(a[1]), "r"(a[2]), "r"(a[3]), "r"(b0), "r"(b1));
}
__device__ __forceinline__ void ldsm_x4(uint32_t d[4], uint32_t addr) {
    asm volatile("ldmatrix.sync.aligned.m8n8.x4.shared.b16 {%0,%1,%2,%3}, [%4];"
                 : "=r"(d[0]), "=r"(d[1]), "=r"(d[2]), "=r"(d[3]) : "r"(addr));
}
__device__ __forceinline__ void cpa16(uint32_t saddr, const void* gptr, bool valid) {
    const int sz = valid ? 16 : 0;
    asm volatile("cp.async.cg.shared.global [%0], [%1], 16, %2;"
                 :: "r"(saddr), "l"(gptr), "r"(sz));
}
#define CP_COMMIT()  asm volatile("cp.async.commit_group;")
#define CP_WAIT2()   asm volatile("cp.async.wait_group 2;")

// fast 2^y for y <= 0, FMA pipe only. |rel err| ~3e-6.
__device__ __forceinline__ float exp2p(float y) {
    y = fmaxf(y, -80.f);
    const int ni = __float2int_rn(y);
    const float f = y - (float)ni;
    float p = 0.0013333558146428443f;
    p = fmaf(p, f, 0.009618129107628477f);
    p = fmaf(p, f, 0.05550410866482158f);
    p = fmaf(p, f, 0.2402265069591007f);
    p = fmaf(p, f, 0.6931471805599453f);
    p = fmaf(p, f, 1.0f);
    return __uint_as_float(__float_as_uint(p) + ((uint32_t)ni << 23));
}

// ---------------- conversion kernels ----------------
__global__ __launch_bounds__(256) void cvt_f32_f16(
    const float* __restrict__ src, __half* __restrict__ dst, int n4)
{
    const int i = blockIdx.x * 256 + threadIdx.x;
    if (i < n4) {
        float4 v = reinterpret_cast<const float4*>(src)[i];
        uint2 u;
        u.x = f2h2(v.x, v.y);
        u.y = f2h2(v.z, v.w);
        reinterpret_cast<uint2*>(dst)[i] = u;
    }
}

// fused grid-stride conversion (x, in_proj_w -> fp16)
__global__ __launch_bounds__(256) void cvt_all(
    const float* __restrict__ x, const float* __restrict__ wi,
    __half* __restrict__ dx, __half* __restrict__ dwi)
{
    const int stride = gridDim.x * 256;
    for (int i = blockIdx.x * 256 + threadIdx.x; i < NTOT4; i += stride) {
        const float4* s;
        uint2* d;
        int j;
        if (i < NX4) {
            s = reinterpret_cast<const float4*>(x);   d = reinterpret_cast<uint2*>(dx);   j = i;
        } else {
            s = reinterpret_cast<const float4*>(wi);  d = reinterpret_cast<uint2*>(dwi);  j = i - NX4;
        }
        const float4 v = s[j];
        uint2 u;
        u.x = f2h2(v.x, v.y);
        u.y = f2h2(v.z, v.w);
        d[j] = u;
    }
}

// transpose + convert: src [Kd][Nd] fp32 -> dst [Nd][Kd] fp16, per expert (blockIdx.z)
__global__ __launch_bounds__(256) void transpose_cvt(
    const float* __restrict__ src, __half* __restrict__ dst, int Kd, int Nd)
{
    __shared__ float t[64][33];
    const size_t eofs = (size_t)blockIdx.z * (size_t)Kd * Nd;
    const int n0 = blockIdx.x * 32;
    const int k0 = blockIdx.y * 64;
    const int tx = threadIdx.x & 31;
    const int ty = threadIdx.x >> 5;   // 0..7
#pragma unroll
    for (int i = 0; i < 8; ++i)
        t[ty + i * 8][tx] = src[eofs + (size_t)(k0 + ty + i * 8) * Nd + n0 + tx];
    __syncthreads();
    const int nl = threadIdx.x >> 3;   // 0..31
    const int kc = threadIdx.x & 7;    // 0..7
    __half* drow = dst + eofs + (size_t)(n0 + nl) * Kd + k0;
#pragma unroll
    for (int j = 0; j < 4; ++j) {
        const int k2 = kc + j * 8;     // half2 index 0..31
        __half2 h = __floats2half2_rn(t[2 * k2][nl], t[2 * k2 + 1][nl]);
        *reinterpret_cast<__half2*>(drow + 2 * k2) = h;
    }
}

// ================= fp16 GEMM: 4 warps x (64x64), cp.async 4-stage, ldmatrix ========
constexpr int G_ASTG = 2560;                 // [128][20] words per stage
constexpr int G_BOFF = 4 * G_ASTG;           // 10240
constexpr int GEMM_SMEM_BYTES = 8 * G_ASTG * 4;   // 81920 B

template<int MODE>
__global__ void __launch_bounds__(128, 2) gemm_f16(
    const __half* __restrict__ A, int lda,
    const __half* __restrict__ B, int ldb,
    const float* __restrict__ bias,
    void* __restrict__ Cv, int ldc,
    int K, int Nglob)
{
    extern __shared__ uint32_t smw[];
    __shared__ int tok[128];

    const int tid = threadIdx.x;
    const int wid = tid >> 5;           // 0..3
    const int ln  = tid & 31;
    const int wm  = wid >> 1;           // 0..1 -> 64-row slice
    const int wn  = wid & 1;            // 0..1 -> 64-col slice
    const int m0 = blockIdx.x * 128;
    const int n0 = blockIdx.y * 128;

    int seg0 = 0, seg1 = 1 << 30;
    const __half* Bp = B;
    const float* biasp = bias;
    if (MODE >= 2) {
        const int e = blockIdx.z;
        // local prefix scan of g_cnt (route_scan kernel eliminated)
        int s0 = 0;
#pragma unroll
        for (int i = 0; i < NE; ++i) s0 += (i < e) ? g_cnt[i] : 0;
        seg0 = s0; seg1 = s0 + g_cnt[e];
        if (seg0 + m0 >= seg1) return;
        Bp    = B + (size_t)e * K * Nglob;
        biasp = bias + (size_t)e * Nglob;
        {
            const int p = seg0 + m0 + tid;
            tok[tid] = (p < seg1) ? g_order[p] : -1;
        }
        __syncthreads();
    }

    const uint32_t sbase = smem_u32(smw);

    const uint32_t aoff0 = ((uint32_t)(wm * 64 + (ln & 15)) * 20u + (uint32_t)(ln >> 4) * 4u) * 4u;
    const uint32_t brow = (uint32_t)(wn * 64) + (uint32_t)(((ln >> 4) << 3) | (ln & 7));
    const uint32_t boff0 = (brow * 20u + (uint32_t)((ln >> 3) & 1) * 4u) * 4u;

    float acc[4][8][4];
#pragma unroll
    for (int mt = 0; mt < 4; ++mt)
#pragma unroll
        for (int nt = 0; nt < 8; ++nt)
#pragma unroll
            for (int r = 0; r < 4; ++r) acc[mt][nt][r] = 0.f;

    const int nK = K >> 5;

    auto issue = [&](int kt) {
        const int k0 = kt << 5;
        const int s = kt & 3;
        const uint32_t sA = sbase + (s * G_ASTG) * 4;
        const uint32_t sB = sbase + (G_BOFF + s * G_ASTG) * 4;
#pragma unroll
        for (int it = 0; it < 4; ++it) {
            const int idx = tid + it * 128;   // 0..511
            const int row = idx >> 2;         // 0..127
            const int c   = idx & 3;          // 16B chunk
            const __half* ga;
            bool vA = true;
            if (MODE == 2) {
                const int tk = tok[row];
                vA = (tk >= 0);
                ga = A + (size_t)(vA ? tk : 0) * lda + k0 + c * 8;
            } else if (MODE == 3) {
                ga = A + (size_t)(seg0 + m0 + row) * lda + k0 + c * 8;
            } else {
                ga = A + (size_t)(m0 + row) * lda + k0 + c * 8;
            }
            cpa16(sA + (row * 20 + c * 4) * 4, ga, vA);
            const __half* gb = Bp + (size_t)(n0 + row) * ldb + k0 + c * 8;
            cpa16(sB + (row * 20 + c * 4) * 4, gb, true);
        }
    };
    auto compute = [&](int kt) {
        const int s = kt & 3;
        const uint32_t aab = sbase + (s * G_ASTG) * 4 + aoff0;
        const uint32_t bab = sbase + ((G_BOFF + s * G_ASTG)) * 4 + boff0;
#pragma unroll
        for (int ks = 0; ks < 2; ++ks) {
            const uint32_t kofs = (uint32_t)ks * 32u;
            uint32_t af[4][4];
#pragma unroll
            for (int mt = 0; mt < 4; ++mt)
                ldsm_x4(af[mt], aab + (uint32_t)mt * 1280u + kofs);
#pragma unroll
            for (int q = 0; q < 4; ++q) {
                uint32_t bf[4];
                ldsm_x4(bf, bab + (uint32_t)q * 1280u + kofs);
#pragma unroll
                for (int mt = 0; mt < 4; ++mt) {
                    mma_f16(acc[mt][2 * q],     af[mt], bf[0], bf[1]);
                    mma_f16(acc[mt][2 * q + 1], af[mt], bf[2], bf[3]);
                }
            }
        }
    };

    issue(0); CP_COMMIT();
    issue(1); CP_COMMIT();
    issue(2); CP_COMMIT();
    for (int kt = 0; kt < nK; ++kt) {
        CP_WAIT2();
        __syncthreads();
        if (kt + 3 < nK) issue(kt + 3);
        CP_COMMIT();
        compute(kt);
    }

    const int lr = ln >> 2;
    const int lc = ln & 3;
#pragma unroll
    for (int mt = 0; mt < 4; ++mt) {
#pragma unroll
        for (int half = 0; half < 2; ++half) {
            const int lrow = wm * 64 + mt * 16 + half * 8 + lr;
            bool valid = true;
            size_t rowidx = 0;
            if (MODE == 0 || MODE == 1) {
                rowidx = (size_t)(m0 + lrow);
            } else if (MODE == 2) {
                const int p = seg0 + m0 + lrow;
                valid = (p < seg1);
                rowidx = (size_t)p;
            } else {
                const int tk = tok[lrow];
                valid = (tk >= 0);
                rowidx = (size_t)(valid ? tk : 0);
            }
            if (!valid) continue;
#pragma unroll
            for (int nt = 0; nt < 8; ++nt) {
                const int cc = n0 + wn * 64 + nt * 8 + lc * 2;
                float vx = acc[mt][nt][half * 2 + 0] + biasp[cc];
                float vy = acc[mt][nt][half * 2 + 1] + biasp[cc + 1];
                if (MODE == 0) {
                    uint32_t* dst = (uint32_t*)Cv + rowidx * (ldc >> 1) + (cc >> 1);
                    *dst = f2h2(vx, vy);
                } else if (MODE == 2) {
                    vx = fmaxf(vx, 0.f); vy = fmaxf(vy, 0.f);
                    uint32_t* dst = (uint32_t*)Cv + rowidx * (ldc >> 1) + (cc >> 1);
                    *dst = f2h2(vx, vy);
                } else {
                    float2 v; v.x = vx; v.y = vy;
                    *reinterpret_cast<float2*>((float*)Cv + rowidx * ldc + cc) = v;
                }
            }
        }
    }
}

// ================= fp16 flash attention with register-prefetched K/V =================
__global__ void __launch_bounds__(256, 2) flash_attn_f16(
    const __half* __restrict__ qkvh, __half* __restrict__ Oh)
{
    __shared__ uint32_t sQ[128 * 36];
    __shared__ uint32_t sK[64 * 36];
    __shared__ uint32_t sVt[32 * 72];

    const int tid = threadIdx.x;
    const int wid = tid >> 5;
    const int ln  = tid & 31;
    const int lr  = ln >> 2;
    const int lc  = ln & 3;
    const int b   = blockIdx.y >> 4;
    const int h   = blockIdx.y & 15;
    const int q0  = blockIdx.x * 128;
    const int wq  = wid * 16;
    const float qscale = 0.18033688011112042f;   // log2(e) / sqrt(64)

    const uint32_t* qkw = reinterpret_cast<const uint32_t*>(qkvh);   // 1536 words/row

#pragma unroll
    for (int it = 0; it < 4; ++it) {
        const int idx = tid + it * 256;
        const int row = idx >> 3;
        const int c   = idx & 7;
        const uint32_t* src = qkw + (size_t)(b * NS + q0 + row) * 1536 + h * 32 + c * 4;
        *reinterpret_cast<uint4*>(&sQ[row * 36 + c * 4]) = *reinterpret_cast<const uint4*>(src);
    }

    uint4 pk[2];
    uint4 pvlo, pvhi;
    const int krow0 = tid >> 3;
    const int kc0   = tid & 7;
    const int vk2   = tid >> 3;
    const int vdc   = tid & 7;

    auto loadRegs = [&](int kb) {
#pragma unroll
        for (int it = 0; it < 2; ++it) {
            const int row = krow0 + it * 32;
            const uint32_t* src = qkw + (size_t)(b * NS + kb * 64 + row) * 1536 + 512 + h * 32 + kc0 * 4;
            pk[it] = *reinterpret_cast<const uint4*>(src);
        }
        const uint32_t* vb = qkw + (size_t)(b * NS + kb * 64 + 2 * vk2) * 1536 + 1024 + h * 32 + vdc * 4;
        pvlo = *reinterpret_cast<const uint4*>(vb);
        pvhi = *reinterpret_cast<const uint4*>(vb + 1536);
    };
    auto storeRegs = [&]() {
#pragma unroll
        for (int it = 0; it < 2; ++it) {
            const int row = krow0 + it * 32;
            *reinterpret_cast<uint4*>(&sK[row * 36 + kc0 * 4]) = pk[it];
        }
        uint4 w0, w1;
        w0.x = __byte_perm(pvlo.x, pvhi.x, 0x5410); w0.y = __byte_perm(pvlo.x, pvhi.x, 0x7632);
        w0.z = __byte_perm(pvlo.y, pvhi.y, 0x5410); w0.w = __byte_perm(pvlo.y, pvhi.y, 0x7632);
        w1.x = __byte_perm(pvlo.z, pvhi.z, 0x5410); w1.y = __byte_perm(pvlo.z, pvhi.z, 0x7632);
        w1.z = __byte_perm(pvlo.w, pvhi.w, 0x5410); w1.w = __byte_perm(pvlo.w, pvhi.w, 0x7632);
        *reinterpret_cast<uint4*>(&sVt[vk2 * 72 + vdc * 8]) = w0;
        *reinterpret_cast<uint4*>(&sVt[vk2 * 72 + vdc * 8 + 4]) = w1;
    };

    float mr0 = -1e30f, mr1 = -1e30f;
    float l0 = 0.f, l1 = 0.f;
    float o[8][4];
#pragma unroll
    for (int jd = 0; jd < 8; ++jd)
#pragma unroll
        for (int r = 0; r < 4; ++r) o[jd][r] = 0.f;

    loadRegs(0);
    storeRegs();
    __syncthreads();

    for (int kb = 0; kb < 16; ++kb) {
        if (kb + 1 < 16) loadRegs(kb + 1);

        float s[8][4];
#pragma unroll
        for (int jn = 0; jn < 8; ++jn)
#pragma unroll
            for (int r = 0; r < 4; ++r) s[jn][r] = 0.f;
#pragma unroll
        for (int kk = 0; kk < 4; ++kk) {
            uint32_t a[4];
            a[0] = sQ[(wq + lr) * 36 + kk * 8 + lc];
            a[1] = sQ[(wq + lr + 8) * 36 + kk * 8 + lc];
            a[2] = sQ[(wq + lr) * 36 + kk * 8 + 4 + lc];
            a[3] = sQ[(wq + lr + 8) * 36 + kk * 8 + 4 + lc];
#pragma unroll
            for (int jn = 0; jn < 8; ++jn) {
                const uint32_t b0 = sK[(jn * 8 + lr) * 36 + kk * 8 + lc];
                const uint32_t b1 = sK[(jn * 8 + lr) * 36 + kk * 8 + 4 + lc];
                mma_f16(s[jn], a, b0, b1);
            }
        }
#pragma unroll
        for (int jn = 0; jn < 8; ++jn)
#pragma unroll
            for (int r = 0; r < 4; ++r) s[jn][r] *= qscale;

        float mx0 = s[0][0], mx1 = s[0][2];
#pragma unroll
        for (int jn = 0; jn < 8; ++jn) {
            mx0 = fmaxf(mx0, fmaxf(s[jn][0], s[jn][1]));
            mx1 = fmaxf(mx1, fmaxf(s[jn][2], s[jn][3]));
        }
        mx0 = fmaxf(mx0, __shfl_xor_sync(0xffffffffu, mx0, 1));
        mx0 = fmaxf(mx0, __shfl_xor_sync(0xffffffffu, mx0, 2));
        mx1 = fmaxf(mx1, __shfl_xor_sync(0xffffffffu, mx1, 1));
        mx1 = fmaxf(mx1, __shfl_xor_sync(0xffffffffu, mx1, 2));
        const float mn0 = fmaxf(mr0, mx0);
        const float mn1 = fmaxf(mr1, mx1);
        const float c0 = exp2p(mr0 - mn0);
        const float c1 = exp2p(mr1 - mn1);
        mr0 = mn0; mr1 = mn1;
        l0 *= c0; l1 *= c1;
#pragma unroll
        for (int jn = 0; jn < 8; ++jn) {
            s[jn][0] = exp2p(s[jn][0] - mr0);
            s[jn][1] = exp2p(s[jn][1] - mr0);
            s[jn][2] = exp2p(s[jn][2] - mr1);
            s[jn][3] = exp2p(s[jn][3] - mr1);
            l0 += s[jn][0] + s[jn][1];
            l1 += s[jn][2] + s[jn][3];
        }
#pragma unroll
        for (int jd = 0; jd < 8; ++jd) {
            o[jd][0] *= c0; o[jd][1] *= c0;
            o[jd][2] *= c1; o[jd][3] *= c1;
        }

#pragma unroll
        for (int q = 0; q < 4; ++q) {
            uint32_t a[4];
            a[0] = f2h2(s[2 * q][0], s[2 * q][1]);
            a[1] = f2h2(s[2 * q][2], s[2 * q][3]);
            a[2] = f2h2(s[2 * q + 1][0], s[2 * q + 1][1]);
            a[3] = f2h2(s[2 * q + 1][2], s[2 * q + 1][3]);
#pragma unroll
            for (int jd = 0; jd < 8; ++jd) {
                const uint32_t b0 = sVt[(q * 8 + lc) * 72 + jd * 8 + lr];
                const uint32_t b1 = sVt[(q * 8 + 4 + lc) * 72 + jd * 8 + lr];
                mma_f16(o[jd], a, b0, b1);
            }
        }
        __syncthreads();
        if (kb + 1 < 16) {
            storeRegs();
            __syncthreads();
        }
    }

    l0 += __shfl_xor_sync(0xffffffffu, l0, 1);
    l0 += __shfl_xor_sync(0xffffffffu, l0, 2);
    l1 += __shfl_xor_sync(0xffffffffu, l1, 1);
    l1 += __shfl_xor_sync(0xffffffffu, l1, 2);
    const float i0 = 1.f / l0;
    const float i1 = 1.f / l1;
    uint32_t* ow = reinterpret_cast<uint32_t*>(Oh);
    const size_t r0 = (size_t)(b * NS + q0 + wq + lr);
    const size_t r1 = r0 + 8;
#pragma unroll
    for (int jd = 0; jd < 8; ++jd) {
        ow[r0 * 512 + h * 32 + jd * 4 + lc] = f2h2(o[jd][0] * i0, o[jd][1] * i0);
        ow[r1 * 512 + h * 32 + jd * 4 + lc] = f2h2(o[jd][2] * i1, o[jd][3] * i1);
    }
}

// ---------- residual add + LayerNorm, warp-per-token (+ optional fused gate) -------
// 256 thr = 8 warps = 8 tokens/block; lane holds 32 elements; shuffle-only reductions.
template<bool GATE>
__global__ __launch_bounds__(256) void add_ln_g(
    const float* __restrict__ A, const float* __restrict__ R,
    const float* __restrict__ g, const float* __restrict__ bt,
    float* __restrict__ out, __half* __restrict__ out16,
    const float* __restrict__ gw, const float* __restrict__ gb)
{
    const int wid = threadIdx.x >> 5;
    const int ln  = threadIdx.x & 31;
    const int t   = blockIdx.x * 8 + wid;

    const float* Ar = A + (size_t)t * ND;
    const float* Rr = R + (size_t)t * ND;

    float v[32];
    float sum = 0.f;
#pragma unroll
    for (int i = 0; i < 8; ++i) {
        const int col = i * 128 + ln * 4;
        const float4 a4 = *reinterpret_cast<const float4*>(Ar + col);
        const float4 r4 = *reinterpret_cast<const float4*>(Rr + col);
        v[4 * i + 0] = a4.x + r4.x;
        v[4 * i + 1] = a4.y + r4.y;
        v[4 * i + 2] = a4.z + r4.z;
        v[4 * i + 3] = a4.w + r4.w;
        sum += v[4 * i] + v[4 * i + 1] + v[4 * i + 2] + v[4 * i + 3];
    }
#pragma unroll
    for (int off = 16; off; off >>= 1) sum += __shfl_xor_sync(0xffffffffu, sum, off);
    const float mu = sum * (1.f / ND);

    float vs = 0.f;
#pragma unroll
    for (int i = 0; i < 32; ++i) { const float d = v[i] - mu; vs += d * d; }
#pragma unroll
    for (int off = 16; off; off >>= 1) vs += __shfl_xor_sync(0xffffffffu, vs, off);
    const float rstd = rsqrtf(vs * (1.f / ND) + EPS);

    float* Or = out + (size_t)t * ND;
#pragma unroll
    for (int i = 0; i < 8; ++i) {
        const int col = i * 128 + ln * 4;
        const float4 g4 = *reinterpret_cast<const float4*>(g + col);
        const float4 b4 = *reinterpret_cast<const float4*>(bt + col);
        float4 o4;
        o4.x = (v[4 * i + 0] - mu) * rstd * g4.x + b4.x;
        o4.y = (v[4 * i + 1] - mu) * rstd * g4.y + b4.y;
        o4.z = (v[4 * i + 2] - mu) * rstd * g4.z + b4.z;
        o4.w = (v[4 * i + 3] - mu) * rstd * g4.w + b4.w;
        v[4 * i + 0] = o4.x; v[4 * i + 1] = o4.y;
        v[4 * i + 2] = o4.z; v[4 * i + 3] = o4.w;
        *reinterpret_cast<float4*>(Or + col) = o4;
        if (out16) {
            uint2 u;
            u.x = f2h2(o4.x, o4.y);
            u.y = f2h2(o4.z, o4.w);
            *reinterpret_cast<uint2*>(out16 + (size_t)t * ND + col) = u;
        }
    }

    if (GATE) {
        int best = 0;
        float bv = -FLT_MAX;
#pragma unroll
        for (int e = 0; e < NE; ++e) {
            float d = 0.f;
#pragma unroll
            for (int i = 0; i < 8; ++i) {
                const int col = i * 128 + ln * 4;
                const float4 w4 = *reinterpret_cast<const float4*>(gw + (size_t)e * ND + col);
                d += v[4 * i + 0] * w4.x + v[4 * i + 1] * w4.y +
                     v[4 * i + 2] * w4.z + v[4 * i + 3] * w4.w;
            }
#pragma unroll
            for (int off = 16; off; off >>= 1) d += __shfl_xor_sync(0xffffffffu, d, off);
            d += gb[e];
            if (d > bv) { bv = d; best = e; }
        }
        if (ln == 0) {
            g_idx[t] = best;
            atomicAdd(&g_cnt[best], 1);
        }
    }
}

// ---------------- routing ----------------
__global__ void route_init() {
    if (threadIdx.x < NE) { g_cnt[threadIdx.x] = 0; g_pos[threadIdx.x] = 0; }
}

// scatter with local prefix scan of g_cnt (no separate scan kernel)
__global__ __launch_bounds__(256) void route_scatter() {
    const int t = blockIdx.x * 256 + threadIdx.x;
    if (t < NT) {
        const int e = g_idx[t];
        int off = 0;
#pragma unroll
        for (int i = 0; i < NE; ++i) off += (i < e) ? g_cnt[i] : 0;
        const int p = off + atomicAdd(&g_pos[e], 1);
        g_order[p] = t;
    }
}

// ---------------- launcher ----------------
extern "C" void kernel_launch(void* const* d_in, const int* in_sizes, int n_in,
                              void* d_out, int out_size)
{
    const float* x         = (const float*)d_in[0];
    const float* in_proj_w = (const float*)d_in[1];
    const float* in_proj_b = (const float*)d_in[2];
    const float* out_w     = (const float*)d_in[3];
    const float* out_b     = (const float*)d_in[4];
    const float* gate_w    = (const float*)d_in[5];
    const float* gate_b    = (const float*)d_in[6];
    const float* W1        = (const float*)d_in[7];
    const float* b1        = (const float*)d_in[8];
    const float* W2        = (const float*)d_in[9];
    const float* b2        = (const float*)d_in[10];
    const float* ln1_g     = (const float*)d_in[11];
    const float* ln1_b     = (const float*)d_in[12];
    const float* ln2_g     = (const float*)d_in[13];
    const float* ln2_b     = (const float*)d_in[14];
    float* out = (float*)d_out;

    __half *x16, *inwh, *outwh, *w1t, *w2t, *qkvh, *attnoh, *x1h, *hbuf;
    float  *tmp, *x1;
    cudaGetSymbolAddress((void**)&x16,    g_x16);
    cudaGetSymbolAddress((void**)&inwh,   g_inwh);
    cudaGetSymbolAddress((void**)&outwh,  g_outwh);
    cudaGetSymbolAddress((void**)&w1t,    g_w1t);
    cudaGetSymbolAddress((void**)&w2t,    g_w2t);
    cudaGetSymbolAddress((void**)&qkvh,   g_qkvh);
    cudaGetSymbolAddress((void**)&attnoh, g_attnoh);
    cudaGetSymbolAddress((void**)&x1h,    g_x1h);
    cudaGetSymbolAddress((void**)&hbuf,   g_h);
    cudaGetSymbolAddress((void**)&tmp,    g_tmp);
    cudaGetSymbolAddress((void**)&x1,     g_x1);

    cudaFuncSetAttribute(gemm_f16<0>, cudaFuncAttributeMaxDynamicSharedMemorySize, GEMM_SMEM_BYTES);
    cudaFuncSetAttribute(gemm_f16<1>, cudaFuncAttributeMaxDynamicSharedMemorySize, GEMM_SMEM_BYTES);
    cudaFuncSetAttribute(gemm_f16<2>, cudaFuncAttributeMaxDynamicSharedMemorySize, GEMM_SMEM_BYTES);
    cudaFuncSetAttribute(gemm_f16<3>, cudaFuncAttributeMaxDynamicSharedMemorySize, GEMM_SMEM_BYTES);

    // ---- side stream: out_w cvt first, then W1/W2 transposes ----
    cudaStream_t s2 = 0;
    cudaEvent_t evFork = 0, evW = 0, evJoin = 0;
    bool use2 =
        (cudaStreamCreateWithFlags(&s2, cudaStreamNonBlocking) == cudaSuccess) &&
        (cudaEventCreateWithFlags(&evFork, cudaEventDisableTiming) == cudaSuccess) &&
        (cudaEventCreateWithFlags(&evW, cudaEventDisableTiming) == cudaSuccess) &&
        (cudaEventCreateWithFlags(&evJoin, cudaEventDisableTiming) == cudaSuccess);

    route_init<<<1, 32>>>();

    if (use2) {
        cudaEventRecord(evFork, 0);
        cudaStreamWaitEvent(s2, evFork, 0);
        cvt_f32_f16<<<ND * ND / 1024, 256, 0, s2>>>(out_w, outwh, ND * ND / 4);
        cudaEventRecord(evW, s2);
        transpose_cvt<<<dim3(NF / 32, ND / 64, NE), 256, 0, s2>>>(W1, w1t, ND, NF);
        transpose_cvt<<<dim3(ND / 32, NF / 64, NE), 256, 0, s2>>>(W2, w2t, NF, ND);
        cudaEventRecord(evJoin, s2);
    } else {
        cvt_f32_f16<<<ND * ND / 1024, 256>>>(out_w, outwh, ND * ND / 4);
        transpose_cvt<<<dim3(NF / 32, ND / 64, NE), 256>>>(W1, w1t, ND, NF);
        transpose_cvt<<<dim3(ND / 32, NF / 64, NE), 256>>>(W2, w2t, NF, ND);
    }

    // 0) fused conversion (x, in_proj_w) on the main stream
    cvt_all<<<1024, 256>>>(x, in_proj_w, x16, inwh);

    // 1) QKV projection (fp16 out)
    gemm_f16<0><<<dim3(NT / 128, 3 * ND / 128, 1), 128, GEMM_SMEM_BYTES>>>(
        x16, ND, inwh, ND, in_proj_b, qkvh, 3 * ND, ND, 3 * ND);
    // 2) attention (fp16, register-prefetched K/V)
    flash_attn_f16<<<dim3(NS / 128, NB * NH), 256>>>(qkvh, attnoh);
    // 3) output projection (fp32 out)
    if (use2) cudaStreamWaitEvent(0, evW, 0);
    gemm_f16<1><<<dim3(NT / 128, ND / 128, 1), 128, GEMM_SMEM_BYTES>>>(
        attnoh, ND, outwh, ND, out_b, tmp, ND, ND, ND);
    // 4) residual + LN1 + fused router gate (warp-per-token)
    add_ln_g<true><<<NT / 8, 256>>>(tmp, x, ln1_g, ln1_b, x1, x1h, gate_w, gate_b);
    // 5) routing scatter (scan fused into consumers)
    route_scatter<<<NT / 256, 256>>>();
    // join the transpose branch before the MoE GEMMs consume w1t/w2t
    if (use2) cudaStreamWaitEvent(0, evJoin, 0);
    // 6) MoE expert FFN
    gemm_f16<2><<<dim3(NT / 128, NF / 128, NE), 128, GEMM_SMEM_BYTES>>>(
        x1h, ND, w1t, ND, b1, hbuf, NF, ND, NF);
    gemm_f16<3><<<dim3(NT / 128, ND / 128, NE), 128, GEMM_SMEM_BYTES>>>(
        hbuf, NF, w2t, NF, b2, tmp, ND, NF, ND);
    // 7) residual + LN2 -> output
    add_ln_g<false><<<NT / 8, 256>>>(tmp, x1, ln2_g, ln2_b, out, nullptr, nullptr, nullptr);

    (void)in_sizes; (void)n_in; (void)out_size;
}